// round 2
// baseline (speedup 1.0000x reference)
#include <cuda_runtime.h>
#include <math.h>

#define NB 16
#define NN 512
#define NH 64
#define NE 16

// ---------------- scratch ----------------
__device__ float g_hidden[NB*NN*NH];
__device__ float g_hh1[NB*NN*NH];
__device__ float g_hh2[NB*NN*NH];
__device__ float g_nvs[NB*NN*NE];
__device__ float g_nvt[NB*NN*NE];
__device__ float g_M[NB*NN*NN];
__device__ float g_x0[NB*NN*66];
__device__ float g_x0c[NB*NN*66];
__device__ float g_h1[NB*NN*66];
__device__ float g_h2[NB*NN*66];
__device__ float g_z[NB*NN*NH];
__device__ float g_t1[NB*4*NN*2];
__device__ float g_t2[NB*4*NN*2];
__device__ float g_tar[NB*NN*32];
__device__ float g_gat[NB*NN*2];

__global__ void k_zero(){
    int i = blockIdx.x*blockDim.x + threadIdx.x;
    if (i < NB*NN*NH) g_hidden[i] = 0.f;
}

// ---------------- generic GCN GEMM: Out[b,w,c] = .05*X0 + .95 * sum_v Op[v,w]*Hin[v,c] ----------------
template<int LD, int CEX>
__global__ void k_gemm(const float* __restrict__ Op, long opBS,
                       const float* __restrict__ Hin, const float* __restrict__ X0,
                       float* __restrict__ Out){
    constexpr int BK = 16;
    int b = blockIdx.z, w0 = blockIdx.x*64;
    const float* op  = Op  + (size_t)b*opBS;
    const float* hin = Hin + (size_t)b*NN*LD;
    const float* x0  = X0  + (size_t)b*NN*LD;
    float*       out = Out + (size_t)b*NN*LD;
    __align__(16) __shared__ float As[BK][64];
    __align__(16) __shared__ float Bs[BK][68];
    int tid = threadIdx.x, nt = blockDim.x;
    int tx = tid & 15, ty = tid >> 4;
    int et = tid - 256;
    float acc[4][4] = {};
    float aE0[4] = {}, aE1[4] = {};
    for (int k0 = 0; k0 < NN; k0 += BK){
        for (int idx = tid; idx < BK*64; idx += nt)
            As[idx>>6][idx&63] = op[(size_t)(k0+(idx>>6))*NN + w0 + (idx&63)];
        for (int idx = tid; idx < BK*LD; idx += nt){
            int i = idx/LD, j = idx - i*LD;
            Bs[i][j] = hin[(size_t)(k0+i)*LD + j];
        }
        __syncthreads();
        if (tid < 256){
            #pragma unroll
            for (int k = 0; k < BK; k++){
                float4 a4 = *(const float4*)&As[k][ty*4];
                float4 b4 = *(const float4*)&Bs[k][tx*4];
                float av[4] = {a4.x,a4.y,a4.z,a4.w};
                float bv[4] = {b4.x,b4.y,b4.z,b4.w};
                #pragma unroll
                for (int i = 0; i < 4; i++)
                    #pragma unroll
                    for (int j = 0; j < 4; j++)
                        acc[i][j] += av[i]*bv[j];
            }
        } else if (CEX > 0 && et < 16){
            #pragma unroll
            for (int k = 0; k < BK; k++){
                float4 a4 = *(const float4*)&As[k][(et&15)*4];
                float b0 = Bs[k][64], b1 = Bs[k][65];
                float av[4] = {a4.x,a4.y,a4.z,a4.w};
                #pragma unroll
                for (int i = 0; i < 4; i++){ aE0[i] += av[i]*b0; aE1[i] += av[i]*b1; }
            }
        }
        __syncthreads();
    }
    if (tid < 256){
        #pragma unroll
        for (int i = 0; i < 4; i++){
            size_t ro = (size_t)(w0 + ty*4 + i)*LD;
            #pragma unroll
            for (int j = 0; j < 4; j++){
                size_t o = ro + tx*4 + j;
                out[o] = 0.05f*x0[o] + 0.95f*acc[i][j];
            }
        }
    } else if (CEX > 0 && et < 16){
        #pragma unroll
        for (int i = 0; i < 4; i++){
            size_t ro = (size_t)(w0 + (et&15)*4 + i)*LD;
            out[ro+64] = 0.05f*x0[ro+64] + 0.95f*aE0[i];
            out[ro+65] = 0.05f*x0[ro+65] + 0.95f*aE1[i];
        }
    }
}

// ---------------- gs/gt projection (192x16 x2) + nvs/nvt ----------------
__global__ void k_proj_gs2(const float* __restrict__ W1, const float* __restrict__ B1,
                           const float* __restrict__ W2, const float* __restrict__ B2,
                           const float* __restrict__ Wsrc, const float* __restrict__ Bsrc,
                           const float* __restrict__ Wtgt, const float* __restrict__ Btgt,
                           const float* __restrict__ graph, int gstride){
    int rbase = blockIdx.x*64;
    int tid = threadIdx.x;
    __align__(16) __shared__ float As[16][64];
    __shared__ float Bs1[16][16], Bs2[16][16];
    int tx = tid & 15, ty = tid >> 4;
    float a1[4] = {}, a2[4] = {};
    const float* segs[3] = {g_hidden, g_hh1, g_hh2};
    for (int kc = 0; kc < 192; kc += 16){
        for (int idx = tid; idx < 1024; idx += 256){
            int k = idx >> 6, row = idx & 63;
            int kg = kc + k;
            As[k][row] = segs[kg>>6][(size_t)(rbase+row)*64 + (kg&63)];
        }
        { int k = tid >> 4, e = tid & 15;
          Bs1[k][e] = W1[(kc+k)*16 + e];
          Bs2[k][e] = W2[(kc+k)*16 + e]; }
        __syncthreads();
        #pragma unroll
        for (int k = 0; k < 16; k++){
            float4 a4 = *(const float4*)&As[k][ty*4];
            float w1 = Bs1[k][tx], w2 = Bs2[k][tx];
            float av[4] = {a4.x,a4.y,a4.z,a4.w};
            #pragma unroll
            for (int i = 0; i < 4; i++){ a1[i] += av[i]*w1; a2[i] += av[i]*w2; }
        }
        __syncthreads();
    }
    float b1v = B1[tx], b2v = B2[tx];
    float ws0 = Wsrc[tx], ws1 = Wsrc[16+tx], wt0 = Wtgt[tx], wt1 = Wtgt[16+tx];
    float bsv = Bsrc[tx], btv = Btgt[tx];
    #pragma unroll
    for (int i = 0; i < 4; i++){
        int row = rbase + ty*4 + i;
        int b = row >> 9, n = row & 511;
        float g0 = graph[(size_t)b*gstride + n*2];
        float g1 = graph[(size_t)b*gstride + n*2 + 1];
        float gsv = a1[i] + b1v, gtv = a2[i] + b2v;
        float es = g0*ws0 + g1*ws1 + bsv;
        float etv = g0*wt0 + g1*wt1 + btv;
        g_nvs[(size_t)row*16 + tx] = tanhf(2.f*es*gsv);
        g_nvt[(size_t)row*16 + tx] = tanhf(2.f*etv*gtv);
    }
}

// ---------------- adaptive adjacency M = normalize(relu(tanh(2(P-P^T)))+I) + A ----------------
__global__ void k_adp(const float* __restrict__ A){
    int b = blockIdx.y, n0 = blockIdx.x*8;
    int tid = threadIdx.x;
    __shared__ float sn[8][16], tn[8][16];
    __shared__ float vals[8][512];
    __shared__ float wsum[8][8];
    __shared__ float inv[8];
    if (tid < 128){
        int r = tid >> 4, e = tid & 15;
        sn[r][e] = g_nvs[((size_t)b*512 + n0 + r)*16 + e];
        tn[r][e] = g_nvt[((size_t)b*512 + n0 + r)*16 + e];
    }
    __syncthreads();
    float lsum[8] = {};
    #pragma unroll
    for (int mi = 0; mi < 2; mi++){
        int m = tid + mi*256;
        float sm[16], tm[16];
        const float4* sp = (const float4*)(g_nvs + ((size_t)b*512 + m)*16);
        const float4* tp = (const float4*)(g_nvt + ((size_t)b*512 + m)*16);
        #pragma unroll
        for (int q = 0; q < 4; q++){
            float4 v = sp[q]; sm[q*4]=v.x; sm[q*4+1]=v.y; sm[q*4+2]=v.z; sm[q*4+3]=v.w;
            float4 w = tp[q]; tm[q*4]=w.x; tm[q*4+1]=w.y; tm[q*4+2]=w.z; tm[q*4+3]=w.w;
        }
        #pragma unroll
        for (int r = 0; r < 8; r++){
            float d = 0.f;
            #pragma unroll
            for (int e = 0; e < 16; e++) d += sn[r][e]*tm[e] - tn[r][e]*sm[e];
            float v = tanhf(2.f*d);
            v = fmaxf(v, 0.f);
            if (m == n0 + r) v += 1.f;
            vals[r][m] = v; lsum[r] += v;
        }
    }
    #pragma unroll
    for (int r = 0; r < 8; r++){
        float s = lsum[r];
        for (int o = 16; o > 0; o >>= 1) s += __shfl_xor_sync(0xffffffffu, s, o);
        if ((tid & 31) == 0) wsum[r][tid>>5] = s;
    }
    __syncthreads();
    if (tid < 8){
        float s = 0.f;
        #pragma unroll
        for (int w = 0; w < 8; w++) s += wsum[tid][w];
        inv[tid] = 1.f/s;
    }
    __syncthreads();
    #pragma unroll
    for (int mi = 0; mi < 2; mi++){
        int m = tid + mi*256;
        #pragma unroll
        for (int r = 0; r < 8; r++)
            g_M[((size_t)b*512 + n0 + r)*512 + m] = vals[r][m]*inv[r] + A[(size_t)(n0+r)*512 + m];
    }
}

// ---------------- build x0 = [graph(2) | hidden(64)] ----------------
__global__ void k_build_x0(const float* __restrict__ graph, int gstride){
    int idx = blockIdx.x*blockDim.x + threadIdx.x;
    if (idx >= NB*NN*66) return;
    int c = idx % 66, row = idx / 66;
    float v;
    if (c < 2){
        int b = row >> 9, n = row & 511;
        v = graph[(size_t)b*gstride + n*2 + c];
    } else v = g_hidden[(size_t)row*64 + (c-2)];
    g_x0[idx] = v;
}

// ---------------- z/r (DUAL=1) or c (DUAL=0) projection 198x64 ----------------
template<int DUAL>
__global__ void k_proj_zrc(const float* __restrict__ S0,
                           const float* __restrict__ W1, const float* __restrict__ B1,
                           const float* __restrict__ W2, const float* __restrict__ B2,
                           const float* __restrict__ graph, int gstride){
    int rbase = blockIdx.x*64, tid = threadIdx.x;
    __align__(16) __shared__ float As[18][64];
    __align__(16) __shared__ float Bs1[18][64];
    __align__(16) __shared__ float Bs2[(DUAL?18:1)][64];
    int tx = tid & 15, ty = tid >> 4;
    float ac1[4][4] = {}, ac2[4][4] = {};
    const float* segs[3] = {S0, g_h1, g_h2};
    for (int kc = 0; kc < 198; kc += 18){
        for (int idx = tid; idx < 18*64; idx += 256){
            int k = idx >> 6, row = idx & 63;
            int kg = kc + k, seg = kg/66, c = kg - seg*66;
            As[k][row] = segs[seg][(size_t)(rbase+row)*66 + c];
        }
        for (int idx = tid; idx < 18*64; idx += 256){
            int k = idx >> 6, j = idx & 63;
            Bs1[k][j] = W1[(kc+k)*64 + j];
            if (DUAL) Bs2[k][j] = W2[(kc+k)*64 + j];
        }
        __syncthreads();
        #pragma unroll
        for (int k = 0; k < 18; k++){
            float4 a4 = *(const float4*)&As[k][ty*4];
            float4 w1 = *(const float4*)&Bs1[k][tx*4];
            float av[4] = {a4.x,a4.y,a4.z,a4.w};
            float wv[4] = {w1.x,w1.y,w1.z,w1.w};
            #pragma unroll
            for (int i = 0; i < 4; i++)
                #pragma unroll
                for (int j = 0; j < 4; j++)
                    ac1[i][j] += av[i]*wv[j];
            if (DUAL){
                float4 w2 = *(const float4*)&Bs2[k][tx*4];
                float uv[4] = {w2.x,w2.y,w2.z,w2.w};
                #pragma unroll
                for (int i = 0; i < 4; i++)
                    #pragma unroll
                    for (int j = 0; j < 4; j++)
                        ac2[i][j] += av[i]*uv[j];
            }
        }
        __syncthreads();
    }
    #pragma unroll
    for (int i = 0; i < 4; i++){
        int row = rbase + ty*4 + i;
        #pragma unroll
        for (int j = 0; j < 4; j++){
            int col = tx*4 + j;
            if (DUAL){
                float z = 1.f/(1.f + expf(-(ac1[i][j] + B1[col])));
                float r = 1.f/(1.f + expf(-(ac2[i][j] + B2[col])));
                g_z[(size_t)row*64 + col] = z;
                g_x0c[(size_t)row*66 + 2 + col] = r * g_hidden[(size_t)row*64 + col];
            } else {
                float cc = tanhf(ac1[i][j] + B1[col]);
                size_t hi = (size_t)row*64 + col;
                float zz = g_z[hi];
                g_hidden[hi] = zz*g_hidden[hi] + (1.f - zz)*cc;
            }
        }
    }
    if (DUAL && tid < 128){
        int r = tid >> 1, c = tid & 1;
        int row = rbase + r;
        int b = row >> 9, n = row & 511;
        g_x0c[(size_t)row*66 + c] = graph[(size_t)b*gstride + n*2 + c];
    }
}

// ---------------- attention scores + softmax ----------------
__global__ void k_attn(const float* __restrict__ sample, const float* __restrict__ wq,
                       const float* __restrict__ wk, const float* __restrict__ bias,
                       const float* __restrict__ trans, float* __restrict__ attn){
    int b = blockIdx.z, t = blockIdx.y, n0 = blockIdx.x*8;
    int tid = threadIdx.x;
    __shared__ float ks[512][8];
    __shared__ float qs[8][8];
    __shared__ float sc[8][512];
    __shared__ float wred[8][8];
    __shared__ float rmax[8], rinv[8];
    __shared__ float wkl[16], trl[8];
    if (tid < 16) wkl[tid] = wk[tid];
    if (tid >= 32 && tid < 40) trl[tid-32] = trans[tid-32];
    __syncthreads();
    #pragma unroll
    for (int mi = 0; mi < 2; mi++){
        int m = tid + mi*256;
        size_t si = ((size_t)(b*24 + 20 + t)*512 + m)*2;
        float s0 = sample[si], s1 = sample[si+1];
        #pragma unroll
        for (int d = 0; d < 8; d++) ks[m][d] = s0*wkl[d] + s1*wkl[8+d];
    }
    if (tid < 64){
        int r = tid >> 3, d = tid & 7;
        size_t ti = ((size_t)(b*24 + 23)*512 + n0 + r)*2;
        qs[r][d] = sample[ti]*wq[d] + sample[ti+1]*wq[8+d] + bias[d];
    }
    __syncthreads();
    float lmax[8];
    #pragma unroll
    for (int r = 0; r < 8; r++) lmax[r] = -1e30f;
    #pragma unroll
    for (int mi = 0; mi < 2; mi++){
        int m = tid + mi*256;
        float kk[8];
        #pragma unroll
        for (int d = 0; d < 8; d++) kk[d] = ks[m][d];
        #pragma unroll
        for (int r = 0; r < 8; r++){
            float acc = 0.f;
            #pragma unroll
            for (int d = 0; d < 8; d++) acc += tanhf(qs[r][d] + kk[d]) * trl[d];
            sc[r][m] = acc;
            lmax[r] = fmaxf(lmax[r], acc);
        }
    }
    #pragma unroll
    for (int r = 0; r < 8; r++){
        float v = lmax[r];
        for (int o = 16; o > 0; o >>= 1) v = fmaxf(v, __shfl_xor_sync(0xffffffffu, v, o));
        if ((tid & 31) == 0) wred[r][tid>>5] = v;
    }
    __syncthreads();
    if (tid < 8){
        float v = -1e30f;
        #pragma unroll
        for (int w = 0; w < 8; w++) v = fmaxf(v, wred[tid][w]);
        rmax[tid] = v;
    }
    __syncthreads();
    float lsum[8] = {};
    #pragma unroll
    for (int mi = 0; mi < 2; mi++){
        int m = tid + mi*256;
        #pragma unroll
        for (int r = 0; r < 8; r++){
            float e = expf(sc[r][m] - rmax[r]);
            sc[r][m] = e; lsum[r] += e;
        }
    }
    __syncthreads();
    #pragma unroll
    for (int r = 0; r < 8; r++){
        float s = lsum[r];
        for (int o = 16; o > 0; o >>= 1) s += __shfl_xor_sync(0xffffffffu, s, o);
        if ((tid & 31) == 0) wred[r][tid>>5] = s;
    }
    __syncthreads();
    if (tid < 8){
        float s = 0.f;
        #pragma unroll
        for (int w = 0; w < 8; w++) s += wred[tid][w];
        rinv[tid] = 1.f/s;
    }
    __syncthreads();
    #pragma unroll
    for (int mi = 0; mi < 2; mi++){
        int m = tid + mi*256;
        #pragma unroll
        for (int r = 0; r < 8; r++)
            attn[((size_t)(b*4 + t)*512 + n0 + r)*512 + m] = sc[r][m]*rinv[r];
    }
}

// ---------------- TGN GCN iteration ----------------
__global__ void k_tgn(const float* __restrict__ A, const float* __restrict__ attn,
                      const float* __restrict__ sample, const float* __restrict__ Hin,
                      float* __restrict__ Out, int first){
    int g = blockIdx.y;
    int w = blockIdx.x*256 + threadIdx.x;
    int b = g >> 2, t = g & 3;
    __shared__ float hx[1024];
    const float* xbase = sample + ((size_t)(b*24 + 20 + t)*512)*2;
    for (int v = threadIdx.x; v < 512; v += 256){
        if (first){ hx[v*2] = xbase[v*2]; hx[v*2+1] = xbase[v*2+1]; }
        else { hx[v*2] = Hin[(size_t)g*1024 + v*2]; hx[v*2+1] = Hin[(size_t)g*1024 + v*2 + 1]; }
    }
    __syncthreads();
    const float* at = attn + (size_t)g*512*512;
    float a0 = 0.f, a1 = 0.f;
    for (int v = 0; v < 512; v++){
        float aw = A[(size_t)v*512 + w] + at[(size_t)v*512 + w];
        a0 += hx[v*2]*aw; a1 += hx[v*2+1]*aw;
    }
    Out[(size_t)g*1024 + w*2]     = 0.05f*xbase[w*2]   + 0.95f*a0;
    Out[(size_t)g*1024 + w*2 + 1] = 0.05f*xbase[w*2+1] + 0.95f*a1;
}

// ---------------- TGN output projection + relu + sum_t + gat ----------------
__global__ void k_tgn_out(const float* __restrict__ sample, const float* __restrict__ Wt,
                          const float* __restrict__ bt, const float* __restrict__ Ws,
                          const float* __restrict__ bs, float* __restrict__ out_gat){
    int unit = blockIdx.x*8 + (threadIdx.x >> 5);
    int k = threadIdx.x & 31;
    int b = unit >> 9, n = unit & 511;
    float acc = 0.f;
    #pragma unroll
    for (int t = 0; t < 4; t++){
        int g = b*4 + t;
        size_t xi = ((size_t)(b*24 + 20 + t)*512 + n)*2;
        size_t hi = ((size_t)g*512 + n)*2;
        float o = bt[k]
            + sample[xi]*Wt[k]      + sample[xi+1]*Wt[32+k]
            + g_t1[hi]*Wt[64+k]     + g_t1[hi+1]*Wt[96+k]
            + g_t2[hi]*Wt[128+k]    + g_t2[hi+1]*Wt[160+k];
        acc += fmaxf(o, 0.f);
    }
    g_tar[(size_t)unit*32 + k] = acc;
    float s0 = acc*Ws[k*2], s1 = acc*Ws[k*2+1];
    for (int o = 16; o > 0; o >>= 1){
        s0 += __shfl_xor_sync(0xffffffffu, s0, o);
        s1 += __shfl_xor_sync(0xffffffffu, s1, o);
    }
    if (k == 0){
        float v0 = s0 + bs[0], v1 = s1 + bs[1];
        g_gat[(size_t)unit*2]   = v0; g_gat[(size_t)unit*2+1]   = v1;
        out_gat[(size_t)unit*2] = v0; out_gat[(size_t)unit*2+1] = v1;
    }
}

// ---------------- final projections ----------------
__global__ void k_final(const float* __restrict__ Wl, const float* __restrict__ bl,
                        const float* __restrict__ Wm, const float* __restrict__ bm,
                        float* __restrict__ out_gru, float* __restrict__ out_fin){
    int row = blockIdx.x*256 + threadIdx.x;
    float r0 = bl[0], r1 = bl[1], f0 = bm[0], f1 = bm[1];
    for (int kk = 0; kk < 32; kk++){
        float tv = g_tar[(size_t)row*32 + kk];
        f0 += tv*Wm[kk*2]; f1 += tv*Wm[kk*2+1];
    }
    for (int h = 0; h < 64; h++){
        float hv = g_hidden[(size_t)row*64 + h];
        r0 += hv*Wl[h*2]; r1 += hv*Wl[h*2+1];
        f0 += hv*Wm[(32+h)*2]; f1 += hv*Wm[(32+h)*2+1];
    }
    out_gru[row*2] = r0; out_gru[row*2+1] = r1;
    out_fin[row*2] = f0; out_fin[row*2+1] = f1;
}

// ---------------- host ----------------
extern "C" void kernel_launch(void* const* d_in, const int* in_sizes, int n_in,
                              void* d_out, int out_size){
    const float* sample = (const float*)d_in[0];
    const float* A   = (const float*)d_in[1];
    const float* wq  = (const float*)d_in[2];
    const float* wk  = (const float*)d_in[3];
    const float* ab  = (const float*)d_in[4];
    const float* atr = (const float*)d_in[5];
    const float* Wt  = (const float*)d_in[6];
    const float* bt  = (const float*)d_in[7];
    const float* Wa1 = (const float*)d_in[8];
    const float* ba1 = (const float*)d_in[9];
    const float* Wa2 = (const float*)d_in[10];
    const float* ba2 = (const float*)d_in[11];
    const float* Wse = (const float*)d_in[12];
    const float* bse = (const float*)d_in[13];
    const float* Wte = (const float*)d_in[14];
    const float* bte = (const float*)d_in[15];
    const float* Wgz = (const float*)d_in[16];
    const float* bgz = (const float*)d_in[17];
    const float* Wgr = (const float*)d_in[18];
    const float* bgr = (const float*)d_in[19];
    const float* Wgc = (const float*)d_in[20];
    const float* bgc = (const float*)d_in[21];
    const float* Wsh = (const float*)d_in[22];
    const float* bsh = (const float*)d_in[23];
    const float* Wl  = (const float*)d_in[24];
    const float* bl  = (const float*)d_in[25];
    const float* Wm  = (const float*)d_in[26];
    const float* bm  = (const float*)d_in[27];

    float* out = (float*)d_out;
    float* out_gat  = out;
    float* out_gru  = out + 16384;
    float* out_fin  = out + 32768;
    float* out_attn = out + 49152;

    float *pM, *px0, *px0c, *ph1, *ph2, *phh1, *phh2, *phid, *pt1, *pt2, *pgat;
    cudaGetSymbolAddress((void**)&pM,   g_M);
    cudaGetSymbolAddress((void**)&px0,  g_x0);
    cudaGetSymbolAddress((void**)&px0c, g_x0c);
    cudaGetSymbolAddress((void**)&ph1,  g_h1);
    cudaGetSymbolAddress((void**)&ph2,  g_h2);
    cudaGetSymbolAddress((void**)&phh1, g_hh1);
    cudaGetSymbolAddress((void**)&phh2, g_hh2);
    cudaGetSymbolAddress((void**)&phid, g_hidden);
    cudaGetSymbolAddress((void**)&pt1,  g_t1);
    cudaGetSymbolAddress((void**)&pt2,  g_t2);
    cudaGetSymbolAddress((void**)&pgat, g_gat);

    auto gru = [&](const float* graph, int gstride){
        k_gemm<64,0><<<dim3(8,1,16),256>>>(A, 0, phid, phid, phh1);
        k_gemm<64,0><<<dim3(8,1,16),256>>>(A, 0, phh1, phid, phh2);
        k_proj_gs2<<<128,256>>>(Wa1,ba1,Wa2,ba2,Wse,bse,Wte,bte,graph,gstride);
        k_adp<<<dim3(64,16),256>>>(A);
        k_build_x0<<<2112,256>>>(graph, gstride);
        k_gemm<66,2><<<dim3(8,1,16),288>>>(pM, 512L*512, px0, px0, ph1);
        k_gemm<66,2><<<dim3(8,1,16),288>>>(pM, 512L*512, ph1, px0, ph2);
        k_proj_zrc<1><<<128,256>>>(px0, Wgz,bgz,Wgr,bgr, graph,gstride);
        k_gemm<66,2><<<dim3(8,1,16),288>>>(pM, 512L*512, px0c, px0c, ph1);
        k_gemm<66,2><<<dim3(8,1,16),288>>>(pM, 512L*512, ph1, px0c, ph2);
        k_proj_zrc<0><<<128,256>>>(px0c, Wgc,bgc, (const float*)0,(const float*)0,
                                   (const float*)0, 0);
    };

    k_zero<<<2048,256>>>();
    for (int s = 0; s < 5; s++)
        gru(sample + (size_t)4*s*1024, 24576);

    k_attn<<<dim3(64,4,16),256>>>(sample, wq, wk, ab, atr, out_attn);
    k_tgn<<<dim3(2,64),256>>>(A, out_attn, sample, (const float*)0, pt1, 1);
    k_tgn<<<dim3(2,64),256>>>(A, out_attn, sample, pt1, pt2, 0);
    k_tgn_out<<<1024,256>>>(sample, Wt, bt, Wsh, bsh, out_gat);

    gru(pgat, 1024);
    k_final<<<32,256>>>(Wl, bl, Wm, bm, out_gru, out_fin);
}